// round 4
// baseline (speedup 1.0000x reference)
#include <cuda_runtime.h>
#include <cstdint>

// Problem constants
#define T_STEPS 32
#define BATCH   512
#define ACT     64
#define POP     64
#define OUT_DIM 4096   // ACT*POP

// Packed fp32x2 ops (Blackwell sm_103a; ptxas never auto-fuses these)
#define FMA2(d, a, b, c) \
    asm("fma.rn.f32x2 %0, %1, %2, %3;" : "=l"(d) : "l"(a), "l"(b), "l"(c))
#define ADD2(d, a, b) \
    asm("add.rn.f32x2 %0, %1, %2;" : "=l"(d) : "l"(a), "l"(b))
#define UNPACK2(lo, hi, p) \
    asm("mov.b64 {%0, %1}, %2;" : "=f"(lo), "=f"(hi) : "l"(p))

__global__ void __launch_bounds__(128, 2)
ilc_snn_kernel(const float* __restrict__ x_seq,   // [T, B, OUT_DIM]
               const float* __restrict__ conn_w,  // [ACT, POP(o), POP(d)]
               const float* __restrict__ conn_b,  // [OUT_DIM]
               float* __restrict__ out)           // [T, B, OUT_DIM]
{
    __shared__ __align__(16) float Wt[64 * 64];   // Wt[d][o]  (transposed)
    __shared__ __align__(16) float bias_s[64];

    const int tid   = threadIdx.x;
    const int a     = blockIdx.x & 63;        // group
    const int chunk = blockIdx.x >> 6;        // batch chunk
    const int b     = chunk * 128 + tid;      // batch index for this thread

    // ---- Load W[a] transposed into smem: Wt[d*64 + o] = w[a, o, d] ----
    {
        const float* gw = conn_w + a * 4096;
        #pragma unroll
        for (int i = tid; i < 4096; i += 128) {
            int o = i >> 6;
            int d = i & 63;
            Wt[d * 64 + o] = gw[i];
        }
        if (tid < 64) bias_s[tid] = conn_b[a * 64 + tid];
    }
    __syncthreads();

    // ---- Per-thread state: v[64] scalar, fb packed as 32 x f32x2 ----
    float v[64];
    unsigned long long fbp[32];
    #pragma unroll
    for (int o = 0; o < 64; ++o) v[o] = 0.0f;
    #pragma unroll
    for (int j = 0; j < 32; ++j) fbp[j] = 0ull;   // fb0 = 0 (no bias at t=0)

    const size_t base = (size_t)b * OUT_DIM + (size_t)a * 64;
    const size_t tstr = (size_t)BATCH * OUT_DIM;  // stride between timesteps

    // Prefetch x for t = 0
    float4 xr[16];
    {
        const float4* xp = (const float4*)(x_seq + base);
        #pragma unroll
        for (int j = 0; j < 16; ++j) xr[j] = xp[j];
    }

    for (int t = 0; t < T_STEPS; ++t) {
        // ---------- Phase 1: elementwise IF update + spike write ----------
        unsigned m0 = 0u, m1 = 0u;  // 64-bit spike mask
        float4* op = (float4*)(out + (size_t)t * tstr + base);

        #pragma unroll
        for (int j = 0; j < 16; ++j) {
            float4 x = xr[j];
            float f0, f1, f2, f3;
            UNPACK2(f0, f1, fbp[2 * j]);
            UNPACK2(f2, f3, fbp[2 * j + 1]);

            // v = v + (x_t + fb)   (reference order)
            float v0 = v[4 * j + 0] + (x.x + f0);
            float v1 = v[4 * j + 1] + (x.y + f1);
            float v2 = v[4 * j + 2] + (x.z + f2);
            float v3 = v[4 * j + 3] + (x.w + f3);

            bool s0 = (v0 >= 1.0f);
            bool s1 = (v1 >= 1.0f);
            bool s2 = (v2 >= 1.0f);
            bool s3 = (v3 >= 1.0f);

            float4 o4;
            o4.x = s0 ? 1.0f : 0.0f;
            o4.y = s1 ? 1.0f : 0.0f;
            o4.z = s2 ? 1.0f : 0.0f;
            o4.w = s3 ? 1.0f : 0.0f;
            op[j] = o4;

            // hard reset
            v[4 * j + 0] = s0 ? 0.0f : v0;
            v[4 * j + 1] = s1 ? 0.0f : v1;
            v[4 * j + 2] = s2 ? 0.0f : v2;
            v[4 * j + 3] = s3 ? 0.0f : v3;

            // pack spike bits (compile-time shifts under full unroll)
            if (j < 8) {
                m0 |= ((unsigned)s0) << (4 * j + 0);
                m0 |= ((unsigned)s1) << (4 * j + 1);
                m0 |= ((unsigned)s2) << (4 * j + 2);
                m0 |= ((unsigned)s3) << (4 * j + 3);
            } else {
                m1 |= ((unsigned)s0) << (4 * j - 32);
                m1 |= ((unsigned)s1) << (4 * j - 31);
                m1 |= ((unsigned)s2) << (4 * j - 30);
                m1 |= ((unsigned)s3) << (4 * j - 29);
            }
        }

        // ---------- Prefetch x for t+1 (hidden under the matmul) ----------
        if (t + 1 < T_STEPS) {
            const float4* xp = (const float4*)(x_seq + (size_t)(t + 1) * tstr + base);
            #pragma unroll
            for (int j = 0; j < 16; ++j) xr[j] = xp[j];
        }

        // ---------- Phase 2: fb_new[o] = sum_{d: spike} Wt[d][o]  (+bias) ----------
        #pragma unroll
        for (int j = 0; j < 32; ++j) fbp[j] = 0ull;

        #pragma unroll
        for (int d = 0; d < 64; ++d) {
            unsigned bit = (d < 32) ? ((m0 >> d) & 1u) : ((m1 >> (d - 32)) & 1u);
            // packed (1.0f,1.0f) or (0,0); product with W is exact -> matches ref mul+sum
            unsigned long long s2p = bit ? 0x3f8000003f800000ull : 0ull;
            const ulonglong2* wr = (const ulonglong2*)(Wt + (d << 6));
            #pragma unroll
            for (int j = 0; j < 16; ++j) {
                ulonglong2 w = wr[j];                 // LDS.128, warp-broadcast
                FMA2(fbp[2 * j],     w.x, s2p, fbp[2 * j]);
                FMA2(fbp[2 * j + 1], w.y, s2p, fbp[2 * j + 1]);
            }
        }

        // bias added after the reduction (reference order: einsum(...) + bias)
        const unsigned long long* bp = (const unsigned long long*)bias_s;
        #pragma unroll
        for (int j = 0; j < 32; ++j) {
            ADD2(fbp[j], fbp[j], bp[j]);
        }
    }
}

extern "C" void kernel_launch(void* const* d_in, const int* in_sizes, int n_in,
                              void* d_out, int out_size)
{
    const float* x_seq  = (const float*)d_in[0];
    const float* conn_w = (const float*)d_in[1];
    const float* conn_b = (const float*)d_in[2];
    float* out = (float*)d_out;

    // 64 groups x 4 batch-chunks of 128 -> one thread per (batch, group) system
    ilc_snn_kernel<<<256, 128>>>(x_seq, conn_w, conn_b, out);
}

// round 5
// speedup vs baseline: 1.5082x; 1.5082x over previous
#include <cuda_runtime.h>
#include <cstdint>

// Problem constants
#define T_STEPS 32
#define BATCH   512
#define ACT     64
#define POP     64
#define OUT_DIM 4096   // ACT*POP

#define ROWPAD 80      // padded Wt row length in floats (slices at +20-word offsets)

// Packed fp32x2 ops (Blackwell sm_103a)
#define FMA2(d, a, b, c) \
    asm("fma.rn.f32x2 %0, %1, %2, %3;" : "=l"(d) : "l"(a), "l"(b), "l"(c))
#define ADD2(d, a, b) \
    asm("add.rn.f32x2 %0, %1, %2;" : "=l"(d) : "l"(a), "l"(b))
#define UNPACK2(lo, hi, p) \
    asm("mov.b64 {%0, %1}, %2;" : "=f"(lo), "=f"(hi) : "l"(p))

__global__ void __launch_bounds__(128, 4)
ilc_snn_kernel(const float* __restrict__ x_seq,   // [T, B, OUT_DIM]
               const float* __restrict__ conn_w,  // [ACT, POP(o), POP(d)]
               const float* __restrict__ conn_b,  // [OUT_DIM]
               float* __restrict__ out)           // [T, B, OUT_DIM]
{
    // Wt[d] row: 80 floats; slice s (o in [16s,16s+16)) stored at words [20s, 20s+16).
    // Bank sets for the 4 slice addresses: base + {0,20,8,28} mod 32 -> disjoint.
    __shared__ __align__(16) float Wt[64 * ROWPAD];
    __shared__ __align__(16) float bias_s[64];

    const int tid   = threadIdx.x;
    const int lane  = tid & 31;
    const int warp  = tid >> 5;
    const int a     = blockIdx.x & 63;      // group
    const int chunk = blockIdx.x >> 6;      // batch chunk (0..15), 32 batches each
    const int slice = lane >> 3;            // o-slice 0..3 (16 outputs each)
    const int boff  = lane & 7;
    const int b     = chunk * 32 + warp * 8 + boff;

    // ---- Load W[a] transposed+padded: Wt[d*80 + 20*(o>>4) + (o&15)] = w[a,o,d] ----
    {
        const float* gw = conn_w + a * 4096;
        #pragma unroll
        for (int i = tid; i < 4096; i += 128) {
            int o = i >> 6;
            int d = i & 63;
            Wt[d * ROWPAD + 20 * (o >> 4) + (o & 15)] = gw[i];
        }
        if (tid < 64) bias_s[tid] = conn_b[a * 64 + tid];
    }
    __syncthreads();   // only barrier in the kernel

    // ---- Per-thread state: 16 outputs of one system ----
    float v[16];
    unsigned long long fbp[8];
    #pragma unroll
    for (int o = 0; o < 16; ++o) v[o] = 0.0f;
    #pragma unroll
    for (int j = 0; j < 8; ++j) fbp[j] = 0ull;   // fb0 = 0 (no bias at t=0)

    const size_t base = (size_t)b * OUT_DIM + (size_t)a * 64 + (size_t)slice * 16;
    const size_t tstr = (size_t)BATCH * OUT_DIM;

    const float* wslice = Wt + slice * 20;        // per-thread slice base
    const unsigned long long* bp =
        (const unsigned long long*)(bias_s + slice * 16);

    // Prefetch x for t = 0
    float4 xr[4];
    {
        const float4* xp = (const float4*)(x_seq + base);
        #pragma unroll
        for (int j = 0; j < 4; ++j) xr[j] = xp[j];
    }

    for (int t = 0; t < T_STEPS; ++t) {
        // ---------- Phase 1: IF update + spike write (this thread's 16 o's) ----
        unsigned m = 0u;   // 16-bit local spike mask (bits = o - 16*slice)
        float4* op = (float4*)(out + (size_t)t * tstr + base);

        #pragma unroll
        for (int j = 0; j < 4; ++j) {
            float4 x = xr[j];
            float f0, f1, f2, f3;
            UNPACK2(f0, f1, fbp[2 * j]);
            UNPACK2(f2, f3, fbp[2 * j + 1]);

            // v = v + (x_t + fb)   (reference order)
            float v0 = v[4 * j + 0] + (x.x + f0);
            float v1 = v[4 * j + 1] + (x.y + f1);
            float v2 = v[4 * j + 2] + (x.z + f2);
            float v3 = v[4 * j + 3] + (x.w + f3);

            bool s0 = (v0 >= 1.0f);
            bool s1 = (v1 >= 1.0f);
            bool s2 = (v2 >= 1.0f);
            bool s3 = (v3 >= 1.0f);

            float4 o4;
            o4.x = s0 ? 1.0f : 0.0f;
            o4.y = s1 ? 1.0f : 0.0f;
            o4.z = s2 ? 1.0f : 0.0f;
            o4.w = s3 ? 1.0f : 0.0f;
            op[j] = o4;

            v[4 * j + 0] = s0 ? 0.0f : v0;     // hard reset
            v[4 * j + 1] = s1 ? 0.0f : v1;
            v[4 * j + 2] = s2 ? 0.0f : v2;
            v[4 * j + 3] = s3 ? 0.0f : v3;

            m |= ((unsigned)s0) << (4 * j + 0);
            m |= ((unsigned)s1) << (4 * j + 1);
            m |= ((unsigned)s2) << (4 * j + 2);
            m |= ((unsigned)s3) << (4 * j + 3);
        }

        // ---------- Assemble full 64-bit mask across the 4 slice-lanes ----------
        // lanes {l, l^8, l^16, l^24} hold slices {0,1,2,3} of the same batch.
        unsigned r = m << ((slice & 1) * 16);
        r |= __shfl_xor_sync(0xffffffffu, r, 8);       // combine slice pairs (0,1),(2,3)
        unsigned r2 = __shfl_xor_sync(0xffffffffu, r, 16);
        unsigned m_lo = (slice < 2) ? r  : r2;         // spike bits d = 0..31
        unsigned m_hi = (slice < 2) ? r2 : r;          // spike bits d = 32..63

        // ---------- Prefetch x for t+1 (hidden under the matmul) ----------
        if (t + 1 < T_STEPS) {
            const float4* xp = (const float4*)(x_seq + (size_t)(t + 1) * tstr + base);
            #pragma unroll
            for (int j = 0; j < 4; ++j) xr[j] = xp[j];
        }

        // ---------- Phase 2: fb_new[o] = sum_{d asc} s[d]*Wt[d][o], then +bias ----
        #pragma unroll
        for (int j = 0; j < 8; ++j) fbp[j] = 0ull;

        #pragma unroll
        for (int d = 0; d < 64; ++d) {
            unsigned bit = (d < 32) ? ((m_lo >> d) & 1u) : ((m_hi >> (d - 32)) & 1u);
            // (1.0f,1.0f) or (0,0); product exact -> matches ref term-for-term
            unsigned long long s2p = bit ? 0x3f8000003f800000ull : 0ull;
            const ulonglong2* wr = (const ulonglong2*)(wslice + d * ROWPAD);
            ulonglong2 w0 = wr[0];                 // 2x LDS.128, conflict-free
            ulonglong2 w1 = wr[1];
            FMA2(fbp[0], w0.x, s2p, fbp[0]);
            FMA2(fbp[1], w0.y, s2p, fbp[1]);
            FMA2(fbp[2], w1.x, s2p, fbp[2]);
            FMA2(fbp[3], w1.y, s2p, fbp[3]);
            const ulonglong2* wr2 = wr + 2;
            ulonglong2 w2 = wr2[0];
            ulonglong2 w3 = wr2[1];
            FMA2(fbp[4], w2.x, s2p, fbp[4]);
            FMA2(fbp[5], w2.y, s2p, fbp[5]);
            FMA2(fbp[6], w3.x, s2p, fbp[6]);
            FMA2(fbp[7], w3.y, s2p, fbp[7]);
        }

        // bias after the reduction (reference order)
        #pragma unroll
        for (int j = 0; j < 8; ++j) {
            ADD2(fbp[j], fbp[j], bp[j]);
        }
    }
}

extern "C" void kernel_launch(void* const* d_in, const int* in_sizes, int n_in,
                              void* d_out, int out_size)
{
    const float* x_seq  = (const float*)d_in[0];
    const float* conn_w = (const float*)d_in[1];
    const float* conn_b = (const float*)d_in[2];
    float* out = (float*)d_out;

    // 64 groups x 16 batch-chunks of 32; 128 threads = 32 batches x 4 o-slices
    ilc_snn_kernel<<<1024, 128>>>(x_seq, conn_w, conn_b, out);
}

// round 6
// speedup vs baseline: 1.7693x; 1.1731x over previous
#include <cuda_runtime.h>
#include <cstdint>

// Problem constants
#define T_STEPS 32
#define BATCH   512
#define ACT     64
#define POP     64
#define OUT_DIM 4096   // ACT*POP

#define ROWPAD 80      // padded Wt row (floats); slices at +20-word offsets -> disjoint banks

typedef unsigned long long ull;

// Packed fp32x2 ops (Blackwell sm_103a)
#define FMA2(d, a, b, c) \
    asm("fma.rn.f32x2 %0, %1, %2, %3;" : "=l"(d) : "l"(a), "l"(b), "l"(c))
#define ADD2(d, a, b) \
    asm("add.rn.f32x2 %0, %1, %2;" : "=l"(d) : "l"(a), "l"(b))
#define UNPACK2(lo, hi, p) \
    asm("mov.b64 {%0, %1}, %2;" : "=f"(lo), "=f"(hi) : "l"(p))

#define ONES2 0x3f8000003f800000ull

__global__ void __launch_bounds__(128, 3)
ilc_snn_kernel(const float* __restrict__ x_seq,   // [T, B, OUT_DIM]
               const float* __restrict__ conn_w,  // [ACT, POP(o), POP(d)]
               const float* __restrict__ conn_b,  // [OUT_DIM]
               float* __restrict__ out)           // [T, B, OUT_DIM]
{
    // Wt[d] row: 80 floats; slice s (o in [16s,16s+16)) at words [20s,20s+16).
    // The 4 slice addresses per LDS.128 hit disjoint bank sets -> conflict-free.
    __shared__ __align__(16) float Wt[64 * ROWPAD];
    __shared__ __align__(16) float bias_s[64];

    const int tid   = threadIdx.x;
    const int lane  = tid & 31;
    const int warp  = tid >> 5;
    const int a     = blockIdx.x & 63;      // group
    const int chunk = blockIdx.x >> 6;      // batch chunk (0..7), 64 batches each
    const int slice = lane >> 3;            // o-slice 0..3 (16 outputs each)
    const int boff  = lane & 7;
    const int b0    = chunk * 64 + warp * 16 + boff;   // batch 0; batch 1 = b0+8

    // ---- Load W[a] transposed+padded: Wt[d*80 + 20*(o>>4) + (o&15)] = w[a,o,d] ----
    {
        const float* gw = conn_w + a * 4096;
        #pragma unroll
        for (int i = tid; i < 4096; i += 128) {
            int o = i >> 6;
            int d = i & 63;
            Wt[d * ROWPAD + 20 * (o >> 4) + (o & 15)] = gw[i];
        }
        if (tid < 64) bias_s[tid] = conn_b[a * 64 + tid];
    }
    __syncthreads();   // only barrier in the kernel

    // ---- Per-thread state: 2 batches x 16 outputs ----
    float v[2][16];
    ull   fbp[2][8];
    #pragma unroll
    for (int bi = 0; bi < 2; ++bi) {
        #pragma unroll
        for (int o = 0; o < 16; ++o) v[bi][o] = 0.0f;
        #pragma unroll
        for (int j = 0; j < 8; ++j) fbp[bi][j] = 0ull;   // fb0 = 0 (no bias at t=0)
    }

    size_t base[2];
    base[0] = (size_t)b0 * OUT_DIM + (size_t)a * 64 + (size_t)slice * 16;
    base[1] = base[0] + (size_t)8 * OUT_DIM;
    const size_t tstr = (size_t)BATCH * OUT_DIM;

    const float* wslice = Wt + slice * 20;
    const ull* bp = (const ull*)(bias_s + slice * 16);

    // Prefetch x for t = 0 (both batches)
    float4 xr[2][4];
    #pragma unroll
    for (int bi = 0; bi < 2; ++bi) {
        const float4* xp = (const float4*)(x_seq + base[bi]);
        #pragma unroll
        for (int j = 0; j < 4; ++j) xr[bi][j] = xp[j];
    }

    for (int t = 0; t < T_STEPS; ++t) {
        // ---------- Phase 1: IF update + spike write, both batches ----------
        unsigned mloc[2];
        #pragma unroll
        for (int bi = 0; bi < 2; ++bi) {
            unsigned m = 0u;
            float4* op = (float4*)(out + (size_t)t * tstr + base[bi]);

            #pragma unroll
            for (int j = 0; j < 4; ++j) {
                float4 x = xr[bi][j];
                float f0, f1, f2, f3;
                UNPACK2(f0, f1, fbp[bi][2 * j]);
                UNPACK2(f2, f3, fbp[bi][2 * j + 1]);

                // v = v + (x_t + fb)   (reference order)
                float v0 = v[bi][4 * j + 0] + (x.x + f0);
                float v1 = v[bi][4 * j + 1] + (x.y + f1);
                float v2 = v[bi][4 * j + 2] + (x.z + f2);
                float v3 = v[bi][4 * j + 3] + (x.w + f3);

                bool s0 = (v0 >= 1.0f);
                bool s1 = (v1 >= 1.0f);
                bool s2 = (v2 >= 1.0f);
                bool s3 = (v3 >= 1.0f);

                float4 o4;
                o4.x = s0 ? 1.0f : 0.0f;
                o4.y = s1 ? 1.0f : 0.0f;
                o4.z = s2 ? 1.0f : 0.0f;
                o4.w = s3 ? 1.0f : 0.0f;
                op[j] = o4;

                v[bi][4 * j + 0] = s0 ? 0.0f : v0;   // hard reset
                v[bi][4 * j + 1] = s1 ? 0.0f : v1;
                v[bi][4 * j + 2] = s2 ? 0.0f : v2;
                v[bi][4 * j + 3] = s3 ? 0.0f : v3;

                m |= ((unsigned)s0) << (4 * j + 0);
                m |= ((unsigned)s1) << (4 * j + 1);
                m |= ((unsigned)s2) << (4 * j + 2);
                m |= ((unsigned)s3) << (4 * j + 3);
            }
            mloc[bi] = m;
        }

        // ---------- Prefetch x for t+1 (hidden under the matmul) ----------
        if (t + 1 < T_STEPS) {
            #pragma unroll
            for (int bi = 0; bi < 2; ++bi) {
                const float4* xp =
                    (const float4*)(x_seq + (size_t)(t + 1) * tstr + base[bi]);
                #pragma unroll
                for (int j = 0; j < 4; ++j) xr[bi][j] = xp[j];
            }

            // ---------- Assemble 64-bit spike masks across the 4 slice-lanes ----
            // lanes {l, l^8, l^16, l^24} hold slices {0,1,2,3} of the same batches.
            unsigned mlo[2], mhi[2];
            #pragma unroll
            for (int bi = 0; bi < 2; ++bi) {
                unsigned r = mloc[bi] << ((slice & 1) * 16);
                r |= __shfl_xor_sync(0xffffffffu, r, 8);
                unsigned r2 = __shfl_xor_sync(0xffffffffu, r, 16);
                mlo[bi] = (slice < 2) ? r  : r2;     // spike bits d = 0..31
                mhi[bi] = (slice < 2) ? r2 : r;      // spike bits d = 32..63
            }

            // ---------- Phase 2: fb_new[o] = sum_{d asc} s[d]*Wt[d][o], +bias ----
            #pragma unroll
            for (int bi = 0; bi < 2; ++bi)
                #pragma unroll
                for (int j = 0; j < 8; ++j) fbp[bi][j] = 0ull;

            unsigned ml0 = mlo[0], ml1 = mlo[1];
            const float* wrow = wslice;

            #pragma unroll 8
            for (int d = 0; d < 32; ++d) {
                ull s2p0 = (ml0 & 1u) ? ONES2 : 0ull;  ml0 >>= 1;
                ull s2p1 = (ml1 & 1u) ? ONES2 : 0ull;  ml1 >>= 1;
                const ulonglong2* wr = (const ulonglong2*)wrow;
                ulonglong2 w0 = wr[0];                 // 4x LDS.128, conflict-free
                ulonglong2 w1 = wr[1];
                ulonglong2 w2 = wr[2];
                ulonglong2 w3 = wr[3];
                FMA2(fbp[0][0], w0.x, s2p0, fbp[0][0]);
                FMA2(fbp[0][1], w0.y, s2p0, fbp[0][1]);
                FMA2(fbp[0][2], w1.x, s2p0, fbp[0][2]);
                FMA2(fbp[0][3], w1.y, s2p0, fbp[0][3]);
                FMA2(fbp[0][4], w2.x, s2p0, fbp[0][4]);
                FMA2(fbp[0][5], w2.y, s2p0, fbp[0][5]);
                FMA2(fbp[0][6], w3.x, s2p0, fbp[0][6]);
                FMA2(fbp[0][7], w3.y, s2p0, fbp[0][7]);
                FMA2(fbp[1][0], w0.x, s2p1, fbp[1][0]);
                FMA2(fbp[1][1], w0.y, s2p1, fbp[1][1]);
                FMA2(fbp[1][2], w1.x, s2p1, fbp[1][2]);
                FMA2(fbp[1][3], w1.y, s2p1, fbp[1][3]);
                FMA2(fbp[1][4], w2.x, s2p1, fbp[1][4]);
                FMA2(fbp[1][5], w2.y, s2p1, fbp[1][5]);
                FMA2(fbp[1][6], w3.x, s2p1, fbp[1][6]);
                FMA2(fbp[1][7], w3.y, s2p1, fbp[1][7]);
                wrow += ROWPAD;
            }

            unsigned mh0 = mhi[0], mh1 = mhi[1];
            #pragma unroll 8
            for (int d = 0; d < 32; ++d) {
                ull s2p0 = (mh0 & 1u) ? ONES2 : 0ull;  mh0 >>= 1;
                ull s2p1 = (mh1 & 1u) ? ONES2 : 0ull;  mh1 >>= 1;
                const ulonglong2* wr = (const ulonglong2*)wrow;
                ulonglong2 w0 = wr[0];
                ulonglong2 w1 = wr[1];
                ulonglong2 w2 = wr[2];
                ulonglong2 w3 = wr[3];
                FMA2(fbp[0][0], w0.x, s2p0, fbp[0][0]);
                FMA2(fbp[0][1], w0.y, s2p0, fbp[0][1]);
                FMA2(fbp[0][2], w1.x, s2p0, fbp[0][2]);
                FMA2(fbp[0][3], w1.y, s2p0, fbp[0][3]);
                FMA2(fbp[0][4], w2.x, s2p0, fbp[0][4]);
                FMA2(fbp[0][5], w2.y, s2p0, fbp[0][5]);
                FMA2(fbp[0][6], w3.x, s2p0, fbp[0][6]);
                FMA2(fbp[0][7], w3.y, s2p0, fbp[0][7]);
                FMA2(fbp[1][0], w0.x, s2p1, fbp[1][0]);
                FMA2(fbp[1][1], w0.y, s2p1, fbp[1][1]);
                FMA2(fbp[1][2], w1.x, s2p1, fbp[1][2]);
                FMA2(fbp[1][3], w1.y, s2p1, fbp[1][3]);
                FMA2(fbp[1][4], w2.x, s2p1, fbp[1][4]);
                FMA2(fbp[1][5], w2.y, s2p1, fbp[1][5]);
                FMA2(fbp[1][6], w3.x, s2p1, fbp[1][6]);
                FMA2(fbp[1][7], w3.y, s2p1, fbp[1][7]);
                wrow += ROWPAD;
            }

            // bias after the reduction (reference order)
            #pragma unroll
            for (int bi = 0; bi < 2; ++bi)
                #pragma unroll
                for (int j = 0; j < 8; ++j)
                    ADD2(fbp[bi][j], fbp[bi][j], bp[j]);
        }
    }
}

extern "C" void kernel_launch(void* const* d_in, const int* in_sizes, int n_in,
                              void* d_out, int out_size)
{
    const float* x_seq  = (const float*)d_in[0];
    const float* conn_w = (const float*)d_in[1];
    const float* conn_b = (const float*)d_in[2];
    float* out = (float*)d_out;

    // 64 groups x 8 batch-chunks of 64; 128 threads = 32 (batch,slice) lanes x 2 batches
    ilc_snn_kernel<<<512, 128>>>(x_seq, conn_w, conn_b, out);
}

// round 7
// speedup vs baseline: 2.3732x; 1.3414x over previous
#include <cuda_runtime.h>
#include <cstdint>

// Problem constants
#define T_STEPS 32
#define BATCH   512
#define ACT     64
#define POP     64
#define OUT_DIM 4096   // ACT*POP

#define ROWLEN 96      // padded Wt row (floats); 8 slices at +12-float offsets
                       // -> the 8 LDS.128 bank-quads cover all 32 banks once.

typedef unsigned long long ull;

// Packed fp32x2 ops (Blackwell sm_103a)
#define FMA2(d, a, b, c) \
    asm("fma.rn.f32x2 %0, %1, %2, %3;" : "=l"(d) : "l"(a), "l"(b), "l"(c))
#define ADD2(d, a, b) \
    asm("add.rn.f32x2 %0, %1, %2;" : "=l"(d) : "l"(a), "l"(b))
#define UNPACK2(lo, hi, p) \
    asm("mov.b64 {%0, %1}, %2;" : "=f"(lo), "=f"(hi) : "l"(p))

#define ONES2 0x3f8000003f800000ull

__global__ void __launch_bounds__(128, 3)
ilc_snn_kernel(const float* __restrict__ x_seq,   // [T, B, OUT_DIM]
               const float* __restrict__ conn_w,  // [ACT, POP(o), POP(d)]
               const float* __restrict__ conn_b,  // [OUT_DIM]
               float* __restrict__ out)           // [T, B, OUT_DIM]
{
    // Wt[d] row: 96 floats; slice s (o in [8s, 8s+8)) at words [12s, 12s+8).
    __shared__ __align__(16) float Wt[64 * ROWLEN];
    __shared__ __align__(16) float bias_s[64];

    const int tid   = threadIdx.x;
    const int lane  = tid & 31;
    const int warp  = tid >> 5;
    const int a     = blockIdx.x & 63;      // group
    const int chunk = blockIdx.x >> 6;      // batch chunk (0..7), 64 batches each
    const int slice = lane >> 2;            // o-slice 0..7 (8 outputs each)
    const int blane = lane & 3;
    const int b0    = chunk * 64 + warp * 16 + blane;  // batches b0 + {0,4,8,12}

    // ---- Load W[a] transposed+padded: Wt[d*96 + 12*(o>>3) + (o&7)] = w[a,o,d] ----
    {
        const float* gw = conn_w + a * 4096;
        #pragma unroll
        for (int i = tid; i < 4096; i += 128) {
            int o = i >> 6;
            int d = i & 63;
            Wt[d * ROWLEN + 12 * (o >> 3) + (o & 7)] = gw[i];
        }
        if (tid < 64) bias_s[tid] = conn_b[a * 64 + tid];
    }
    __syncthreads();   // only barrier in the kernel

    // ---- Per-thread state: 4 batches x 8 outputs ----
    float v[4][8];
    ull   fbp[4][4];
    #pragma unroll
    for (int k = 0; k < 4; ++k) {
        #pragma unroll
        for (int o = 0; o < 8; ++o) v[k][o] = 0.0f;
        #pragma unroll
        for (int j = 0; j < 4; ++j) fbp[k][j] = 0ull;   // fb0 = 0 (no bias at t=0)
    }

    size_t base[4];
    base[0] = (size_t)b0 * OUT_DIM + (size_t)a * 64 + (size_t)slice * 8;
    base[1] = base[0] + (size_t)4  * OUT_DIM;
    base[2] = base[0] + (size_t)8  * OUT_DIM;
    base[3] = base[0] + (size_t)12 * OUT_DIM;
    const size_t tstr = (size_t)BATCH * OUT_DIM;

    const float* wslice = Wt + slice * 12;
    const ull* bp = (const ull*)(bias_s + slice * 8);

    // Prefetch x for t = 0 (4 batches x 8 floats)
    float4 xr[4][2];
    #pragma unroll
    for (int k = 0; k < 4; ++k) {
        const float4* xp = (const float4*)(x_seq + base[k]);
        xr[k][0] = xp[0];
        xr[k][1] = xp[1];
    }

    for (int t = 0; t < T_STEPS; ++t) {
        // ---------- Phase 1: IF update + spike write, 4 batches ----------
        unsigned mloc[4];
        #pragma unroll
        for (int k = 0; k < 4; ++k) {
            unsigned m = 0u;
            float4* op = (float4*)(out + (size_t)t * tstr + base[k]);

            #pragma unroll
            for (int j = 0; j < 2; ++j) {
                float4 x = xr[k][j];
                float f0, f1, f2, f3;
                UNPACK2(f0, f1, fbp[k][2 * j]);
                UNPACK2(f2, f3, fbp[k][2 * j + 1]);

                // v = v + (x_t + fb)   (reference order)
                float v0 = v[k][4 * j + 0] + (x.x + f0);
                float v1 = v[k][4 * j + 1] + (x.y + f1);
                float v2 = v[k][4 * j + 2] + (x.z + f2);
                float v3 = v[k][4 * j + 3] + (x.w + f3);

                bool s0 = (v0 >= 1.0f);
                bool s1 = (v1 >= 1.0f);
                bool s2 = (v2 >= 1.0f);
                bool s3 = (v3 >= 1.0f);

                float4 o4;
                o4.x = s0 ? 1.0f : 0.0f;
                o4.y = s1 ? 1.0f : 0.0f;
                o4.z = s2 ? 1.0f : 0.0f;
                o4.w = s3 ? 1.0f : 0.0f;
                op[j] = o4;

                v[k][4 * j + 0] = s0 ? 0.0f : v0;   // hard reset
                v[k][4 * j + 1] = s1 ? 0.0f : v1;
                v[k][4 * j + 2] = s2 ? 0.0f : v2;
                v[k][4 * j + 3] = s3 ? 0.0f : v3;

                m |= ((unsigned)s0) << (4 * j + 0);
                m |= ((unsigned)s1) << (4 * j + 1);
                m |= ((unsigned)s2) << (4 * j + 2);
                m |= ((unsigned)s3) << (4 * j + 3);
            }
            mloc[k] = m;
        }

        if (t + 1 < T_STEPS) {
            // ---------- Prefetch x for t+1 (hidden under the matmul) ----------
            #pragma unroll
            for (int k = 0; k < 4; ++k) {
                const float4* xp =
                    (const float4*)(x_seq + (size_t)(t + 1) * tstr + base[k]);
                xr[k][0] = xp[0];
                xr[k][1] = xp[1];
            }

            // ---------- Assemble 64-bit spike masks across the 8 slice-lanes ----
            // lanes {l ^ 4q : q} share blane (same batches); xor 4/8 combines the
            // quad of slices into a 32-bit word, xor 16 swaps quad words.
            unsigned mlo[4], mhi[4];
            #pragma unroll
            for (int k = 0; k < 4; ++k) {
                unsigned r = mloc[k] << (8 * (slice & 3));
                r |= __shfl_xor_sync(0xffffffffu, r, 4);
                r |= __shfl_xor_sync(0xffffffffu, r, 8);
                unsigned r2 = __shfl_xor_sync(0xffffffffu, r, 16);
                mlo[k] = (slice < 4) ? r  : r2;     // spike bits d = 0..31
                mhi[k] = (slice < 4) ? r2 : r;      // spike bits d = 32..63
            }

            // ---------- Phase 2: fb_new[o] = sum_{d asc} s[d]*Wt[d][o], +bias ----
            #pragma unroll
            for (int k = 0; k < 4; ++k)
                #pragma unroll
                for (int j = 0; j < 4; ++j) fbp[k][j] = 0ull;

            unsigned m0 = mlo[0], m1 = mlo[1], m2 = mlo[2], m3 = mlo[3];
            const float* wrow = wslice;

            #pragma unroll 8
            for (int d = 0; d < 32; ++d) {
                ull s0 = (m0 & 1u) ? ONES2 : 0ull;  m0 >>= 1;
                ull s1 = (m1 & 1u) ? ONES2 : 0ull;  m1 >>= 1;
                ull s2 = (m2 & 1u) ? ONES2 : 0ull;  m2 >>= 1;
                ull s3 = (m3 & 1u) ? ONES2 : 0ull;  m3 >>= 1;
                const ulonglong2* wr = (const ulonglong2*)wrow;
                ulonglong2 wA = wr[0];               // 2x LDS.128, conflict-free
                ulonglong2 wB = wr[1];
                FMA2(fbp[0][0], wA.x, s0, fbp[0][0]);
                FMA2(fbp[0][1], wA.y, s0, fbp[0][1]);
                FMA2(fbp[0][2], wB.x, s0, fbp[0][2]);
                FMA2(fbp[0][3], wB.y, s0, fbp[0][3]);
                FMA2(fbp[1][0], wA.x, s1, fbp[1][0]);
                FMA2(fbp[1][1], wA.y, s1, fbp[1][1]);
                FMA2(fbp[1][2], wB.x, s1, fbp[1][2]);
                FMA2(fbp[1][3], wB.y, s1, fbp[1][3]);
                FMA2(fbp[2][0], wA.x, s2, fbp[2][0]);
                FMA2(fbp[2][1], wA.y, s2, fbp[2][1]);
                FMA2(fbp[2][2], wB.x, s2, fbp[2][2]);
                FMA2(fbp[2][3], wB.y, s2, fbp[2][3]);
                FMA2(fbp[3][0], wA.x, s3, fbp[3][0]);
                FMA2(fbp[3][1], wA.y, s3, fbp[3][1]);
                FMA2(fbp[3][2], wB.x, s3, fbp[3][2]);
                FMA2(fbp[3][3], wB.y, s3, fbp[3][3]);
                wrow += ROWLEN;
            }

            m0 = mhi[0]; m1 = mhi[1]; m2 = mhi[2]; m3 = mhi[3];
            #pragma unroll 8
            for (int d = 0; d < 32; ++d) {
                ull s0 = (m0 & 1u) ? ONES2 : 0ull;  m0 >>= 1;
                ull s1 = (m1 & 1u) ? ONES2 : 0ull;  m1 >>= 1;
                ull s2 = (m2 & 1u) ? ONES2 : 0ull;  m2 >>= 1;
                ull s3 = (m3 & 1u) ? ONES2 : 0ull;  m3 >>= 1;
                const ulonglong2* wr = (const ulonglong2*)wrow;
                ulonglong2 wA = wr[0];
                ulonglong2 wB = wr[1];
                FMA2(fbp[0][0], wA.x, s0, fbp[0][0]);
                FMA2(fbp[0][1], wA.y, s0, fbp[0][1]);
                FMA2(fbp[0][2], wB.x, s0, fbp[0][2]);
                FMA2(fbp[0][3], wB.y, s0, fbp[0][3]);
                FMA2(fbp[1][0], wA.x, s1, fbp[1][0]);
                FMA2(fbp[1][1], wA.y, s1, fbp[1][1]);
                FMA2(fbp[1][2], wB.x, s1, fbp[1][2]);
                FMA2(fbp[1][3], wB.y, s1, fbp[1][3]);
                FMA2(fbp[2][0], wA.x, s2, fbp[2][0]);
                FMA2(fbp[2][1], wA.y, s2, fbp[2][1]);
                FMA2(fbp[2][2], wB.x, s2, fbp[2][2]);
                FMA2(fbp[2][3], wB.y, s2, fbp[2][3]);
                FMA2(fbp[3][0], wA.x, s3, fbp[3][0]);
                FMA2(fbp[3][1], wA.y, s3, fbp[3][1]);
                FMA2(fbp[3][2], wB.x, s3, fbp[3][2]);
                FMA2(fbp[3][3], wB.y, s3, fbp[3][3]);
                wrow += ROWLEN;
            }

            // bias after the reduction (reference order)
            #pragma unroll
            for (int k = 0; k < 4; ++k)
                #pragma unroll
                for (int j = 0; j < 4; ++j)
                    ADD2(fbp[k][j], fbp[k][j], bp[j]);
        }
    }
}

extern "C" void kernel_launch(void* const* d_in, const int* in_sizes, int n_in,
                              void* d_out, int out_size)
{
    const float* x_seq  = (const float*)d_in[0];
    const float* conn_w = (const float*)d_in[1];
    const float* conn_b = (const float*)d_in[2];
    float* out = (float*)d_out;

    // 64 groups x 8 batch-chunks of 64; 128 threads = 32 (batch,slice) lanes x 4 batches
    ilc_snn_kernel<<<512, 128>>>(x_seq, conn_w, conn_b, out);
}